// round 8
// baseline (speedup 1.0000x reference)
#include <cuda_runtime.h>
#include <cstdint>

#define DEVINL __device__ __forceinline__

// Problem constants
static const int Bb = 4, Ss = 4096, Dd = 1024, Hh = 16;

// Scratch (static device globals — allocation-free)
__device__ __align__(1024) float g_qkv[16384 * 3072];  // 192 MB [tokens, 3D] (tf32-rounded)
__device__ __align__(1024) float g_ao[16384 * 1024];   // 64 MB  [tokens, D] (tf32-rounded)
__device__ __align__(1024) float g_rx[16384 * 1024];   // 64 MB  rounded input
__device__ __align__(1024) float g_rw[3072 * 1024];    // 12 MB  rounded w_in
__device__ __align__(1024) float g_rwo[1024 * 1024];   // 4 MB   rounded w_out

// ---------------------------------------------------------------------------
// helpers
// ---------------------------------------------------------------------------
DEVINL uint32_t f2tf32(float f) {
    uint32_t u;
    asm("cvt.rna.tf32.f32 %0, %1;" : "=r"(u) : "f"(f));
    return u;
}
DEVINL void mma_tf32(float* c, const uint32_t* a, uint32_t b0, uint32_t b1) {
    asm("mma.sync.aligned.m16n8k8.row.col.f32.tf32.tf32.f32 "
        "{%0,%1,%2,%3}, {%4,%5,%6,%7}, {%8,%9}, {%0,%1,%2,%3};"
        : "+f"(c[0]), "+f"(c[1]), "+f"(c[2]), "+f"(c[3])
        : "r"(a[0]), "r"(a[1]), "r"(a[2]), "r"(a[3]), "r"(b0), "r"(b1));
}
DEVINL uint32_t smem_u32(const void* p) { return (uint32_t)__cvta_generic_to_shared(p); }
DEVINL void cp16(uint32_t dst, const void* src) {
    asm volatile("cp.async.ca.shared.global [%0], [%1], 16;" :: "r"(dst), "l"(src));
}
DEVINL void cp_commit() { asm volatile("cp.async.commit_group;"); }
template<int N> DEVINL void cp_wait() { asm volatile("cp.async.wait_group %0;" :: "n"(N)); }
DEVINL uint32_t fbits(float f) { return __float_as_uint(f); }

// ---------------------------------------------------------------------------
// elementwise tf32 RNA pre-round (makes HMMA operand truncation an identity)
// ---------------------------------------------------------------------------
__global__ void round_tf32_k(const float4* __restrict__ in, float4* __restrict__ out, int n4)
{
    int i = blockIdx.x * blockDim.x + threadIdx.x;
    if (i < n4) {
        float4 v = in[i];
        v.x = __uint_as_float(f2tf32(v.x));
        v.y = __uint_as_float(f2tf32(v.y));
        v.z = __uint_as_float(f2tf32(v.z));
        v.w = __uint_as_float(f2tf32(v.w));
        out[i] = v;
    }
}

// ---------------------------------------------------------------------------
// SIMT tf32 GEMM: C[M,N] = A[M,K] @ W[N,K]^T + bias[N]
// A, W MUST be tf32-pre-rounded. BM=256, BN=128, BK=32, 512 threads,
// 16 warps with 64x32 warp tiles (acc=64 regs). cp.async double buffer.
// No cvt anywhere in the mainloop. round_out!=0 -> write tf32-rounded C.
// ---------------------------------------------------------------------------
__global__ void __launch_bounds__(512, 1)
gemm_simt(const float* __restrict__ A, int lda,
          const float* __restrict__ W, int ldw,
          float* __restrict__ C, int ldc,
          int K, const float* __restrict__ bias, int round_out)
{
    constexpr int LDS_ = 36;
    extern __shared__ float sm[];
    float* As = sm;                    // [2][256][36]
    float* Bs = sm + 2 * 256 * LDS_;   // [2][128][36]

    const int tid = threadIdx.x, lane = tid & 31, wid = tid >> 5;
    const int warpM = (wid & 3) * 64, warpN = (wid >> 2) * 32;
    const long long m0 = (long long)blockIdx.y * 256;
    const long long n0 = (long long)blockIdx.x * 128;

    float acc[4][4][4] = {};

    auto issue = [&](int it, int buf) {
        const long long k0 = (long long)it * 32;
        float* ad = As + buf * 256 * LDS_;
        #pragma unroll
        for (int i = 0; i < 4; ++i) {
            int lin = i * 512 + tid;
            int r = lin >> 3, c4 = (lin & 7) * 4;
            cp16(smem_u32(ad + r * LDS_ + c4), A + (m0 + r) * lda + k0 + c4);
        }
        float* bd = Bs + buf * 128 * LDS_;
        #pragma unroll
        for (int i = 0; i < 2; ++i) {
            int lin = i * 512 + tid;
            int r = lin >> 3, c4 = (lin & 7) * 4;
            cp16(smem_u32(bd + r * LDS_ + c4), W + (n0 + r) * ldw + k0 + c4);
        }
        cp_commit();
    };

    const int NIT = K / 32;
    issue(0, 0);
    int buf = 0;
    for (int it = 0; it < NIT; ++it) {
        cp_wait<0>();
        __syncthreads();
        if (it + 1 < NIT) issue(it + 1, buf ^ 1);

        const float* a = As + buf * 256 * LDS_;
        const float* b = Bs + buf * 128 * LDS_;
        #pragma unroll
        for (int kk = 0; kk < 32; kk += 8) {
            const int kb = kk + (lane & 3);
            uint32_t af[4][4];
            #pragma unroll
            for (int im = 0; im < 4; ++im) {
                int r = warpM + im * 16 + (lane >> 2);
                af[im][0] = fbits(a[r * LDS_ + kb]);
                af[im][1] = fbits(a[(r + 8) * LDS_ + kb]);
                af[im][2] = fbits(a[r * LDS_ + kb + 4]);
                af[im][3] = fbits(a[(r + 8) * LDS_ + kb + 4]);
            }
            #pragma unroll
            for (int in = 0; in < 4; ++in) {
                int nn = warpN + in * 8 + (lane >> 2);
                uint32_t b0 = fbits(b[nn * LDS_ + kb]);
                uint32_t b1 = fbits(b[nn * LDS_ + kb + 4]);
                #pragma unroll
                for (int im = 0; im < 4; ++im)
                    mma_tf32(acc[im][in], af[im], b0, b1);
            }
        }
        buf ^= 1;
    }

    #pragma unroll
    for (int im = 0; im < 4; ++im) {
        long long r = m0 + warpM + im * 16 + (lane >> 2);
        #pragma unroll
        for (int in = 0; in < 4; ++in) {
            long long c = n0 + warpN + in * 8 + 2 * (lane & 3);
            float b0 = bias[c], b1 = bias[c + 1];
            float v0 = acc[im][in][0] + b0, v1 = acc[im][in][1] + b1;
            float v2 = acc[im][in][2] + b0, v3 = acc[im][in][3] + b1;
            if (round_out) {
                v0 = __uint_as_float(f2tf32(v0));
                v1 = __uint_as_float(f2tf32(v1));
                v2 = __uint_as_float(f2tf32(v2));
                v3 = __uint_as_float(f2tf32(v3));
            }
            *(float2*)&C[r * ldc + c]       = make_float2(v0, v1);
            *(float2*)&C[(r + 8) * ldc + c] = make_float2(v2, v3);
        }
    }
}

// ---------------------------------------------------------------------------
// Fused attention (r3 structure). qkv is tf32-pre-rounded -> all operand
// loads are raw bits (zero cvt in mainloops). P rounded once at sP store.
// smem floats: sQ[128][68] @0, sK[128][68] @8704, sV[128][72] @17408,
//              sP[128][132] @26624 -> 43520 f = 174080 B
// ---------------------------------------------------------------------------
__global__ void __launch_bounds__(256, 1)
attn_fused(const float* __restrict__ qkv, float* __restrict__ ao, int W, int nc)
{
    extern __shared__ float sm[];
    float* sQ = sm;
    float* sK = sm + 8704;
    float* sV = sm + 17408;
    float* sP = sm + 26624;

    const int tid = threadIdx.x, lane = tid & 31, wid = tid >> 5;
    const int pair = blockIdx.y;
    const int win = pair >> 4, h = pair & 15;
    const int q0 = blockIdx.x * 128;
    const long long base = (long long)win * W * 3072 + h * 64;
    const float* Qg = qkv + base + (long long)q0 * 3072;
    const float* Kg = qkv + base + 1024;
    const float* Vg = qkv + base + 2048;

    #pragma unroll
    for (int i = 0; i < 8; ++i) {
        int lin = i * 256 + tid;
        int r = lin >> 4, c4 = (lin & 15) * 4;
        cp16(smem_u32(sQ + r * 68 + c4), Qg + (long long)r * 3072 + c4);
    }
    cp_commit();

    float oacc[8][4] = {};
    float m_[2] = {-1e30f, -1e30f}, l_[2] = {0.f, 0.f};
    const int rw0 = q0 + wid * 16 + (lane >> 2);

    for (int c = 0; c < nc; ++c) {
        const float* Kc = Kg + (long long)c * 128 * 3072;
        const float* Vc = Vg + (long long)c * 128 * 3072;
        #pragma unroll
        for (int i = 0; i < 8; ++i) {
            int lin = i * 256 + tid;
            int r = lin >> 4, c4 = (lin & 15) * 4;
            cp16(smem_u32(sK + r * 68 + c4), Kc + (long long)r * 3072 + c4);
        }
        #pragma unroll
        for (int i = 0; i < 8; ++i) {
            int lin = i * 256 + tid;
            int r = lin >> 4, c4 = (lin & 15) * 4;
            cp16(smem_u32(sV + r * 72 + c4), Vc + (long long)r * 3072 + c4);
        }
        cp_commit();
        cp_wait<0>();
        __syncthreads();

        // ---- S = Q K^T ----
        float sacc[16][4];
        #pragma unroll
        for (int i = 0; i < 16; ++i)
            sacc[i][0] = sacc[i][1] = sacc[i][2] = sacc[i][3] = 0.f;

        #pragma unroll
        for (int kk = 0; kk < 64; kk += 8) {
            const int kb = kk + (lane & 3);
            const int r = wid * 16 + (lane >> 2);
            uint32_t af[4];
            af[0] = fbits(sQ[r * 68 + kb]);
            af[1] = fbits(sQ[(r + 8) * 68 + kb]);
            af[2] = fbits(sQ[r * 68 + kb + 4]);
            af[3] = fbits(sQ[(r + 8) * 68 + kb + 4]);
            #pragma unroll
            for (int in = 0; in < 16; ++in) {
                int nn = in * 8 + (lane >> 2);
                uint32_t b0 = fbits(sK[nn * 68 + kb]);
                uint32_t b1 = fbits(sK[nn * 68 + kb + 4]);
                mma_tf32(sacc[in], af, b0, b1);
            }
        }

        // ---- online softmax (ADDITIVE +1.0 mask for col > row) ----
        float scale0 = 0.f, scale1 = 0.f;
        #pragma unroll
        for (int hh = 0; hh < 2; ++hh) {
            const int rw = rw0 + hh * 8;
            float cm = -1e30f;
            #pragma unroll
            for (int in = 0; in < 16; ++in) {
                int col = c * 128 + in * 8 + 2 * (lane & 3);
                float v0 = sacc[in][2 * hh]     * 0.125f + ((col     > rw) ? 1.f : 0.f);
                float v1 = sacc[in][2 * hh + 1] * 0.125f + ((col + 1 > rw) ? 1.f : 0.f);
                sacc[in][2 * hh] = v0; sacc[in][2 * hh + 1] = v1;
                cm = fmaxf(cm, fmaxf(v0, v1));
            }
            cm = fmaxf(cm, __shfl_xor_sync(0xffffffffu, cm, 1));
            cm = fmaxf(cm, __shfl_xor_sync(0xffffffffu, cm, 2));
            float mn = fmaxf(m_[hh], cm);
            float sc = __expf(m_[hh] - mn);
            float rs = 0.f;
            const int rloc = wid * 16 + (lane >> 2) + hh * 8;
            #pragma unroll
            for (int in = 0; in < 16; ++in) {
                float p0 = __expf(sacc[in][2 * hh] - mn);
                float p1 = __expf(sacc[in][2 * hh + 1] - mn);
                rs += p0 + p1;
                // store tf32-rounded so PV reads raw bits
                *(float2*)&sP[rloc * 132 + in * 8 + 2 * (lane & 3)] = make_float2(
                    __uint_as_float(f2tf32(p0)), __uint_as_float(f2tf32(p1)));
            }
            rs += __shfl_xor_sync(0xffffffffu, rs, 1);
            rs += __shfl_xor_sync(0xffffffffu, rs, 2);
            l_[hh] = l_[hh] * sc + rs;
            m_[hh] = mn;
            if (hh == 0) scale0 = sc; else scale1 = sc;
        }
        #pragma unroll
        for (int in = 0; in < 8; ++in) {
            oacc[in][0] *= scale0; oacc[in][1] *= scale0;
            oacc[in][2] *= scale1; oacc[in][3] *= scale1;
        }
        __syncwarp();

        // ---- O += P V ----
        #pragma unroll
        for (int kk = 0; kk < 128; kk += 8) {
            const int kb = kk + (lane & 3);
            const int r = wid * 16 + (lane >> 2);
            uint32_t af[4];
            af[0] = fbits(sP[r * 132 + kb]);
            af[1] = fbits(sP[(r + 8) * 132 + kb]);
            af[2] = fbits(sP[r * 132 + kb + 4]);
            af[3] = fbits(sP[(r + 8) * 132 + kb + 4]);
            #pragma unroll
            for (int in = 0; in < 8; ++in) {
                int nn = in * 8 + (lane >> 2);
                uint32_t b0 = fbits(sV[kb * 72 + nn]);
                uint32_t b1 = fbits(sV[(kb + 4) * 72 + nn]);
                mma_tf32(oacc[in], af, b0, b1);
            }
        }
        __syncthreads();
    }

    // ---- epilogue: O /= l, tf32-rounded (feeds out-proj raw) ----
    const float inv0 = 1.f / l_[0], inv1 = 1.f / l_[1];
    const long long trow = (long long)win * W + q0 + wid * 16 + (lane >> 2);
    float* Od = ao + trow * 1024 + h * 64;
    #pragma unroll
    for (int in = 0; in < 8; ++in) {
        int cc = in * 8 + 2 * (lane & 3);
        *(float2*)&Od[cc] = make_float2(
            __uint_as_float(f2tf32(oacc[in][0] * inv0)),
            __uint_as_float(f2tf32(oacc[in][1] * inv0)));
        *(float2*)&Od[8 * 1024 + cc] = make_float2(
            __uint_as_float(f2tf32(oacc[in][2] * inv1)),
            __uint_as_float(f2tf32(oacc[in][3] * inv1)));
    }
}

// ---------------------------------------------------------------------------
// driver
// ---------------------------------------------------------------------------
static const int GEMM_SMEM = (2 * 256 * 36 + 2 * 128 * 36) * 4;  // 110592
static const int ATTN_SMEM = 43520 * 4;                           // 174080

static void run_branch(const float* x, const float* w_in, const float* b_in,
                       const float* w_out, const float* b_out,
                       int W, float* out,
                       float* qkv, float* ao, float* rX, float* rW, float* rWo)
{
    // pre-round to tf32 (RNA): HMMA truncation becomes identity -> no cvt in loops
    round_tf32_k<<<16384, 256>>>((const float4*)x, (float4*)rX, 16384 * 1024 / 4);
    round_tf32_k<<<3072, 256>>>((const float4*)w_in, (float4*)rW, 3072 * 1024 / 4);
    round_tf32_k<<<1024, 256>>>((const float4*)w_out, (float4*)rWo, 1024 * 1024 / 4);

    // QKV projection (writes tf32-rounded qkv)
    gemm_simt<<<dim3(3072 / 128, 16384 / 256), 512, GEMM_SMEM>>>(
        rX, Dd, rW, Dd, qkv, 3072, Dd, b_in, 1);

    attn_fused<<<dim3(W / 128, (16384 / W) * Hh), 256, ATTN_SMEM>>>(qkv, ao, W, W / 128);

    // out projection (plain fp32 output)
    gemm_simt<<<dim3(1024 / 128, 16384 / 256), 512, GEMM_SMEM>>>(
        ao, Dd, rWo, Dd, out, Dd, Dd, b_out, 0);
}

extern "C" void kernel_launch(void* const* d_in, const int* in_sizes, int n_in,
                              void* d_out, int out_size)
{
    const float* lqs    = (const float*)d_in[0];
    const float* gqs    = (const float*)d_in[1];
    const float* wl_in  = (const float*)d_in[2];
    const float* bl_in  = (const float*)d_in[3];
    const float* wl_out = (const float*)d_in[4];
    const float* bl_out = (const float*)d_in[5];
    const float* wg_in  = (const float*)d_in[6];
    const float* bg_in  = (const float*)d_in[7];
    const float* wg_out = (const float*)d_in[8];
    const float* bg_out = (const float*)d_in[9];
    float* out = (float*)d_out;

    cudaFuncSetAttribute(gemm_simt, cudaFuncAttributeMaxDynamicSharedMemorySize, GEMM_SMEM);
    cudaFuncSetAttribute(attn_fused, cudaFuncAttributeMaxDynamicSharedMemorySize, ATTN_SMEM);

    float *qkv, *ao, *rX, *rW, *rWo;
    cudaGetSymbolAddress((void**)&qkv, g_qkv);
    cudaGetSymbolAddress((void**)&ao, g_ao);
    cudaGetSymbolAddress((void**)&rX, g_rx);
    cudaGetSymbolAddress((void**)&rW, g_rw);
    cudaGetSymbolAddress((void**)&rWo, g_rwo);

    run_branch(lqs, wl_in, bl_in, wl_out, bl_out, 128, out, qkv, ao, rX, rW, rWo);
    run_branch(gqs, wg_in, bg_in, wg_out, bg_out, 1024,
               out + (size_t)Bb * Ss * Dd, qkv, ao, rX, rW, rWo);
}

// round 10
// speedup vs baseline: 1.6219x; 1.6219x over previous
#include <cuda_runtime.h>
#include <cstdint>

#define DEVINL __device__ __forceinline__

// Problem constants
static const int Bb = 4, Ss = 4096, Dd = 1024, Hh = 16;

// Scratch (static device globals — allocation-free)
__device__ __align__(1024) float g_qkv[16384 * 3072];  // 192 MB [tokens, 3D] (tf32-rounded)
__device__ __align__(1024) float g_ao[16384 * 1024];   // 64 MB  [tokens, D] (tf32-rounded)
__device__ __align__(1024) float g_rx[16384 * 1024];   // rounded input
__device__ __align__(1024) float g_rw[3072 * 1024];    // rounded w_in
__device__ __align__(1024) float g_rwo[1024 * 1024];   // rounded w_out

// ---------------------------------------------------------------------------
// helpers
// ---------------------------------------------------------------------------
DEVINL uint32_t f2tf32(float f) {
    uint32_t u;
    asm("cvt.rna.tf32.f32 %0, %1;" : "=r"(u) : "f"(f));
    return u;
}
DEVINL void mma_tf32(float* c, const uint32_t* a, uint32_t b0, uint32_t b1) {
    asm("mma.sync.aligned.m16n8k8.row.col.f32.tf32.tf32.f32 "
        "{%0,%1,%2,%3}, {%4,%5,%6,%7}, {%8,%9}, {%0,%1,%2,%3};"
        : "+f"(c[0]), "+f"(c[1]), "+f"(c[2]), "+f"(c[3])
        : "r"(a[0]), "r"(a[1]), "r"(a[2]), "r"(a[3]), "r"(b0), "r"(b1));
}
DEVINL uint32_t smem_u32(const void* p) { return (uint32_t)__cvta_generic_to_shared(p); }
DEVINL void cp16(uint32_t dst, const void* src) {
    asm volatile("cp.async.ca.shared.global [%0], [%1], 16;" :: "r"(dst), "l"(src));
}
DEVINL void cp_commit() { asm volatile("cp.async.commit_group;"); }
template<int N> DEVINL void cp_wait() { asm volatile("cp.async.wait_group %0;" :: "n"(N)); }
DEVINL uint32_t fbits(float f) { return __float_as_uint(f); }

// ---------------------------------------------------------------------------
// elementwise tf32 RNA pre-round (HMMA operand truncation becomes identity)
// ---------------------------------------------------------------------------
__global__ void round_tf32_k(const float4* __restrict__ in, float4* __restrict__ out, int n4)
{
    int i = blockIdx.x * blockDim.x + threadIdx.x;
    if (i < n4) {
        float4 v = in[i];
        v.x = __uint_as_float(f2tf32(v.x));
        v.y = __uint_as_float(f2tf32(v.y));
        v.z = __uint_as_float(f2tf32(v.z));
        v.w = __uint_as_float(f2tf32(v.w));
        out[i] = v;
    }
}

// ---------------------------------------------------------------------------
// SIMT tf32 GEMM: C[M,N] = A[M,K] @ W[N,K]^T + bias[N]
// A, W pre-rounded. BM=256, BN=128, BK=32, 256 thr, 8 warps of 64x64
// (128 B smem / MMA = crossbar minimum). cp.async smem double buffer
// + REGISTER FRAGMENT double buffer so LDS(kk+1) overlaps MMA(kk).
// ---------------------------------------------------------------------------
__global__ void __launch_bounds__(256, 1)
gemm_simt(const float* __restrict__ A, int lda,
          const float* __restrict__ W, int ldw,
          float* __restrict__ C, int ldc,
          int K, const float* __restrict__ bias, int round_out)
{
    constexpr int LDS_ = 36;
    extern __shared__ float sm[];
    float* As = sm;                    // [2][256][36]
    float* Bs = sm + 2 * 256 * LDS_;   // [2][128][36]

    const int tid = threadIdx.x, lane = tid & 31, wid = tid >> 5;
    const int warpM = (wid & 3) * 64, warpN = (wid >> 2) * 64;
    const long long m0 = (long long)blockIdx.y * 256;
    const long long n0 = (long long)blockIdx.x * 128;

    float acc[4][8][4] = {};

    auto issue = [&](int it, int buf) {
        const long long k0 = (long long)it * 32;
        float* ad = As + buf * 256 * LDS_;
        #pragma unroll
        for (int i = 0; i < 8; ++i) {
            int lin = i * 256 + tid;
            int r = lin >> 3, c4 = (lin & 7) * 4;
            cp16(smem_u32(ad + r * LDS_ + c4), A + (m0 + r) * lda + k0 + c4);
        }
        float* bd = Bs + buf * 128 * LDS_;
        #pragma unroll
        for (int i = 0; i < 4; ++i) {
            int lin = i * 256 + tid;
            int r = lin >> 3, c4 = (lin & 7) * 4;
            cp16(smem_u32(bd + r * LDS_ + c4), W + (n0 + r) * ldw + k0 + c4);
        }
        cp_commit();
    };

    const int NIT = K / 32;
    issue(0, 0);
    int buf = 0;

    uint32_t af[2][4][4], bf[2][8][2];

    for (int it = 0; it < NIT; ++it) {
        cp_wait<0>();
        __syncthreads();
        if (it + 1 < NIT) issue(it + 1, buf ^ 1);

        const float* a = As + buf * 256 * LDS_;
        const float* b = Bs + buf * 128 * LDS_;

        auto ldfrag = [&](int d, int kk8) {
            const int kb = kk8 * 8 + (lane & 3);
            #pragma unroll
            for (int im = 0; im < 4; ++im) {
                int r = warpM + im * 16 + (lane >> 2);
                af[d][im][0] = fbits(a[r * LDS_ + kb]);
                af[d][im][1] = fbits(a[(r + 8) * LDS_ + kb]);
                af[d][im][2] = fbits(a[r * LDS_ + kb + 4]);
                af[d][im][3] = fbits(a[(r + 8) * LDS_ + kb + 4]);
            }
            #pragma unroll
            for (int in = 0; in < 8; ++in) {
                int nn = warpN + in * 8 + (lane >> 2);
                bf[d][in][0] = fbits(b[nn * LDS_ + kb]);
                bf[d][in][1] = fbits(b[nn * LDS_ + kb + 4]);
            }
        };

        ldfrag(0, 0);
        #pragma unroll
        for (int kk8 = 0; kk8 < 4; ++kk8) {
            const int cur = kk8 & 1;
            if (kk8 < 3) ldfrag(cur ^ 1, kk8 + 1);   // overlaps with MMAs below
            #pragma unroll
            for (int in = 0; in < 8; ++in)
                #pragma unroll
                for (int im = 0; im < 4; ++im)
                    mma_tf32(acc[im][in], af[cur][im], bf[cur][in][0], bf[cur][in][1]);
        }
        buf ^= 1;
    }

    #pragma unroll
    for (int im = 0; im < 4; ++im) {
        long long r = m0 + warpM + im * 16 + (lane >> 2);
        #pragma unroll
        for (int in = 0; in < 8; ++in) {
            long long c = n0 + warpN + in * 8 + 2 * (lane & 3);
            float b0 = bias[c], b1 = bias[c + 1];
            float v0 = acc[im][in][0] + b0, v1 = acc[im][in][1] + b1;
            float v2 = acc[im][in][2] + b0, v3 = acc[im][in][3] + b1;
            if (round_out) {
                v0 = __uint_as_float(f2tf32(v0));
                v1 = __uint_as_float(f2tf32(v1));
                v2 = __uint_as_float(f2tf32(v2));
                v3 = __uint_as_float(f2tf32(v3));
            }
            *(float2*)&C[r * ldc + c]       = make_float2(v0, v1);
            *(float2*)&C[(r + 8) * ldc + c] = make_float2(v2, v3);
        }
    }
}

// ---------------------------------------------------------------------------
// Fused attention v2. Template TM = Q-rows per warp (16 local, 32 global).
// CTA: QT=8*TM Q-rows, key chunks of 64, warp owns TM rows x all 64 cols
// (softmax reductions stay in-warp). KV cp.async double buffered.
// smem floats: sQ[QT][68] | sP[QT][68] | sK[2][64][68] | sV[2][64][72]
// ---------------------------------------------------------------------------
template<int TM>
__global__ void __launch_bounds__(256, 1)
attn2(const float* __restrict__ qkv, float* __restrict__ ao, int W, int nc)
{
    constexpr int QT = TM * 8;
    constexpr int MT = TM / 16;   // m16 blocks per warp (1 or 2)
    constexpr int NH = TM / 8;    // row-groups per lane (2 or 4): hh=(im,half)
    extern __shared__ float sm[];
    float* sQ = sm;                       // QT x 68
    float* sP = sQ + QT * 68;             // QT x 68
    float* sK = sP + QT * 68;             // 2 x 64 x 68
    float* sV = sK + 2 * 64 * 68;         // 2 x 64 x 72

    const int tid = threadIdx.x, lane = tid & 31, wid = tid >> 5;
    const int wm = wid * TM;
    const int pair = blockIdx.y;
    const int win = pair >> 4, h = pair & 15;
    const int q0 = blockIdx.x * QT;       // window-relative
    const long long base = (long long)win * W * 3072 + h * 64;
    const float* Qg = qkv + base + (long long)q0 * 3072;
    const float* Kg = qkv + base + 1024;
    const float* Vg = qkv + base + 2048;

    // stage Q
    #pragma unroll
    for (int i = 0; i < QT / 16; ++i) {   // QT*16 cp16 / 256 thr
        int lin = i * 256 + tid;
        int r = lin >> 4, c4 = (lin & 15) * 4;
        cp16(smem_u32(sQ + r * 68 + c4), Qg + (long long)r * 3072 + c4);
    }
    cp_commit();

    auto stageKV = [&](int c, int b) {
        #pragma unroll
        for (int i = 0; i < 4; ++i) {
            int lin = i * 256 + tid;
            int r = lin >> 4, c4 = (lin & 15) * 4;
            cp16(smem_u32(sK + b * 64 * 68 + r * 68 + c4),
                 Kg + (long long)(c * 64 + r) * 3072 + c4);
        }
        #pragma unroll
        for (int i = 0; i < 4; ++i) {
            int lin = i * 256 + tid;
            int r = lin >> 4, c4 = (lin & 15) * 4;
            cp16(smem_u32(sV + b * 64 * 72 + r * 72 + c4),
                 Vg + (long long)(c * 64 + r) * 3072 + c4);
        }
        cp_commit();
    };
    stageKV(0, 0);

    float oacc[MT][8][4] = {};
    float m_[NH], l_[NH];
    #pragma unroll
    for (int i = 0; i < NH; ++i) { m_[i] = -1e30f; l_[i] = 0.f; }

    for (int c = 0; c < nc; ++c) {
        const int buf = c & 1;
        if (c + 1 < nc) { stageKV(c + 1, buf ^ 1); cp_wait<1>(); }
        else            { cp_wait<0>(); }
        __syncthreads();

        const float* kbuf = sK + buf * 64 * 68;
        const float* vbuf = sV + buf * 64 * 72;

        // ---- S = Q K^T (warp: TM rows x 64 keys) ----
        float sacc[MT][8][4];
        #pragma unroll
        for (int im = 0; im < MT; ++im)
            #pragma unroll
            for (int in = 0; in < 8; ++in)
                sacc[im][in][0] = sacc[im][in][1] = sacc[im][in][2] = sacc[im][in][3] = 0.f;

        #pragma unroll
        for (int kk8 = 0; kk8 < 8; ++kk8) {
            const int kb = kk8 * 8 + (lane & 3);
            uint32_t af[MT][4];
            #pragma unroll
            for (int im = 0; im < MT; ++im) {
                int r = wm + im * 16 + (lane >> 2);
                af[im][0] = fbits(sQ[r * 68 + kb]);
                af[im][1] = fbits(sQ[(r + 8) * 68 + kb]);
                af[im][2] = fbits(sQ[r * 68 + kb + 4]);
                af[im][3] = fbits(sQ[(r + 8) * 68 + kb + 4]);
            }
            #pragma unroll
            for (int in = 0; in < 8; ++in) {
                int nn = in * 8 + (lane >> 2);
                uint32_t b0 = fbits(kbuf[nn * 68 + kb]);
                uint32_t b1 = fbits(kbuf[nn * 68 + kb + 4]);
                #pragma unroll
                for (int im = 0; im < MT; ++im)
                    mma_tf32(sacc[im][in], af[im], b0, b1);
            }
        }

        // ---- online softmax (ADDITIVE +1.0 mask for col > row) ----
        float sscale[NH];
        #pragma unroll
        for (int hh = 0; hh < NH; ++hh) {
            const int im = hh >> 1, half = hh & 1;
            const int rw = q0 + wm + im * 16 + (lane >> 2) + 8 * half;
            float cm = -1e30f;
            #pragma unroll
            for (int in = 0; in < 8; ++in) {
                int col = c * 64 + in * 8 + 2 * (lane & 3);
                float v0 = sacc[im][in][2 * half]     * 0.125f + ((col     > rw) ? 1.f : 0.f);
                float v1 = sacc[im][in][2 * half + 1] * 0.125f + ((col + 1 > rw) ? 1.f : 0.f);
                sacc[im][in][2 * half] = v0; sacc[im][in][2 * half + 1] = v1;
                cm = fmaxf(cm, fmaxf(v0, v1));
            }
            cm = fmaxf(cm, __shfl_xor_sync(0xffffffffu, cm, 1));
            cm = fmaxf(cm, __shfl_xor_sync(0xffffffffu, cm, 2));
            float mn = fmaxf(m_[hh], cm);
            float sc = __expf(m_[hh] - mn);
            float rs = 0.f;
            const int rloc = wm + im * 16 + (lane >> 2) + 8 * half;
            #pragma unroll
            for (int in = 0; in < 8; ++in) {
                float p0 = __expf(sacc[im][in][2 * half] - mn);
                float p1 = __expf(sacc[im][in][2 * half + 1] - mn);
                rs += p0 + p1;
                *(float2*)&sP[rloc * 68 + in * 8 + 2 * (lane & 3)] = make_float2(
                    __uint_as_float(f2tf32(p0)), __uint_as_float(f2tf32(p1)));
            }
            rs += __shfl_xor_sync(0xffffffffu, rs, 1);
            rs += __shfl_xor_sync(0xffffffffu, rs, 2);
            l_[hh] = l_[hh] * sc + rs;
            m_[hh] = mn;
            sscale[hh] = sc;
        }
        #pragma unroll
        for (int im = 0; im < MT; ++im)
            #pragma unroll
            for (int in = 0; in < 8; ++in) {
                oacc[im][in][0] *= sscale[2 * im];
                oacc[im][in][1] *= sscale[2 * im];
                oacc[im][in][2] *= sscale[2 * im + 1];
                oacc[im][in][3] *= sscale[2 * im + 1];
            }
        __syncwarp();   // sP rows are warp-private

        // ---- O += P V (warp: TM rows x 64 dims, k = 64 keys) ----
        #pragma unroll
        for (int kk8 = 0; kk8 < 8; ++kk8) {
            const int kb = kk8 * 8 + (lane & 3);
            uint32_t af[MT][4];
            #pragma unroll
            for (int im = 0; im < MT; ++im) {
                int r = wm + im * 16 + (lane >> 2);
                af[im][0] = fbits(sP[r * 68 + kb]);
                af[im][1] = fbits(sP[(r + 8) * 68 + kb]);
                af[im][2] = fbits(sP[r * 68 + kb + 4]);
                af[im][3] = fbits(sP[(r + 8) * 68 + kb + 4]);
            }
            #pragma unroll
            for (int in = 0; in < 8; ++in) {
                int nn = in * 8 + (lane >> 2);
                uint32_t b0 = fbits(vbuf[kb * 72 + nn]);
                uint32_t b1 = fbits(vbuf[(kb + 4) * 72 + nn]);
                #pragma unroll
                for (int im = 0; im < MT; ++im)
                    mma_tf32(oacc[im][in], af[im], b0, b1);
            }
        }
        __syncthreads();   // KV buffer reuse safety
    }

    // ---- epilogue: O /= l, tf32-rounded (feeds out-proj raw) ----
    #pragma unroll
    for (int im = 0; im < MT; ++im)
        #pragma unroll
        for (int half = 0; half < 2; ++half) {
            const int hh = 2 * im + half;
            const float inv = 1.f / l_[hh];
            const long long trow = (long long)win * W + q0 + wm + im * 16
                                   + (lane >> 2) + 8 * half;
            float* Od = ao + trow * 1024 + h * 64;
            #pragma unroll
            for (int in = 0; in < 8; ++in) {
                int cc = in * 8 + 2 * (lane & 3);
                *(float2*)&Od[cc] = make_float2(
                    __uint_as_float(f2tf32(oacc[im][in][2 * half] * inv)),
                    __uint_as_float(f2tf32(oacc[im][in][2 * half + 1] * inv)));
            }
        }
}

// ---------------------------------------------------------------------------
// driver
// ---------------------------------------------------------------------------
static const int GEMM_SMEM = (2 * 256 * 36 + 2 * 128 * 36) * 4;          // 110592
static const int ATTN16_SMEM = (2 * 128 * 68 + 2 * 64 * 68 + 2 * 64 * 72) * 4;  // 141312
static const int ATTN32_SMEM = (2 * 256 * 68 + 2 * 64 * 68 + 2 * 64 * 72) * 4;  // 210944

static void run_branch(const float* x, const float* w_in, const float* b_in,
                       const float* w_out, const float* b_out,
                       int W, float* out,
                       float* qkv, float* ao, float* rX, float* rW, float* rWo)
{
    round_tf32_k<<<16384, 256>>>((const float4*)x, (float4*)rX, 16384 * 1024 / 4);
    round_tf32_k<<<3072, 256>>>((const float4*)w_in, (float4*)rW, 3072 * 1024 / 4);
    round_tf32_k<<<1024, 256>>>((const float4*)w_out, (float4*)rWo, 1024 * 1024 / 4);

    gemm_simt<<<dim3(3072 / 128, 16384 / 256), 256, GEMM_SMEM>>>(
        rX, Dd, rW, Dd, qkv, 3072, Dd, b_in, 1);

    if (W == 128)
        attn2<16><<<dim3(1, (16384 / 128) * Hh), 256, ATTN16_SMEM>>>(qkv, ao, W, W / 64);
    else
        attn2<32><<<dim3(W / 256, (16384 / W) * Hh), 256, ATTN32_SMEM>>>(qkv, ao, W, W / 64);

    gemm_simt<<<dim3(1024 / 128, 16384 / 256), 256, GEMM_SMEM>>>(
        ao, Dd, rWo, Dd, out, Dd, Dd, b_out, 0);
}

extern "C" void kernel_launch(void* const* d_in, const int* in_sizes, int n_in,
                              void* d_out, int out_size)
{
    const float* lqs    = (const float*)d_in[0];
    const float* gqs    = (const float*)d_in[1];
    const float* wl_in  = (const float*)d_in[2];
    const float* bl_in  = (const float*)d_in[3];
    const float* wl_out = (const float*)d_in[4];
    const float* bl_out = (const float*)d_in[5];
    const float* wg_in  = (const float*)d_in[6];
    const float* bg_in  = (const float*)d_in[7];
    const float* wg_out = (const float*)d_in[8];
    const float* bg_out = (const float*)d_in[9];
    float* out = (float*)d_out;

    cudaFuncSetAttribute(gemm_simt, cudaFuncAttributeMaxDynamicSharedMemorySize, GEMM_SMEM);
    cudaFuncSetAttribute(attn2<16>, cudaFuncAttributeMaxDynamicSharedMemorySize, ATTN16_SMEM);
    cudaFuncSetAttribute(attn2<32>, cudaFuncAttributeMaxDynamicSharedMemorySize, ATTN32_SMEM);

    float *qkv, *ao, *rX, *rW, *rWo;
    cudaGetSymbolAddress((void**)&qkv, g_qkv);
    cudaGetSymbolAddress((void**)&ao, g_ao);
    cudaGetSymbolAddress((void**)&rX, g_rx);
    cudaGetSymbolAddress((void**)&rW, g_rw);
    cudaGetSymbolAddress((void**)&rWo, g_rwo);

    run_branch(lqs, wl_in, bl_in, wl_out, bl_out, 128, out, qkv, ao, rX, rW, rWo);
    run_branch(gqs, wg_in, bg_in, wg_out, bg_out, 1024,
               out + (size_t)Bb * Ss * Dd, qkv, ao, rX, rW, rWo);
}

// round 11
// speedup vs baseline: 2.9589x; 1.8243x over previous
#include <cuda_runtime.h>
#include <cuda_fp16.h>
#include <cstdint>

#define DEVINL __device__ __forceinline__

// Problem constants
static const int Bb = 4, Ss = 4096, Dd = 1024, Hh = 16;

// Scratch (static device globals — allocation-free)
__device__ __align__(1024) __half g_qkvh[16384 * 3072];  // 96 MB [tokens, 3D] fp16
__device__ __align__(1024) __half g_aoh[16384 * 1024];   // 32 MB [tokens, D]  fp16
__device__ __align__(1024) __half g_rxh[16384 * 1024];   // fp16 input
__device__ __align__(1024) __half g_rwh[3072 * 1024];    // fp16 w_in
__device__ __align__(1024) __half g_rwoh[1024 * 1024];   // fp16 w_out

// ---------------------------------------------------------------------------
// helpers
// ---------------------------------------------------------------------------
DEVINL void mma_h(float* c, const uint32_t* a, uint32_t b0, uint32_t b1) {
    asm("mma.sync.aligned.m16n8k16.row.col.f32.f16.f16.f32 "
        "{%0,%1,%2,%3}, {%4,%5,%6,%7}, {%8,%9}, {%0,%1,%2,%3};"
        : "+f"(c[0]), "+f"(c[1]), "+f"(c[2]), "+f"(c[3])
        : "r"(a[0]), "r"(a[1]), "r"(a[2]), "r"(a[3]), "r"(b0), "r"(b1));
}
DEVINL uint32_t smem_u32(const void* p) { return (uint32_t)__cvta_generic_to_shared(p); }
DEVINL void cp16(uint32_t dst, const void* src) {
    asm volatile("cp.async.ca.shared.global [%0], [%1], 16;" :: "r"(dst), "l"(src));
}
DEVINL void cp_commit() { asm volatile("cp.async.commit_group;"); }
template<int N> DEVINL void cp_wait() { asm volatile("cp.async.wait_group %0;" :: "n"(N)); }
DEVINL uint32_t ldh2(const __half* p) { return *(const uint32_t*)p; }
DEVINL void sth2(__half* p, float a, float b) {
    __half2 h = __floats2half2_rn(a, b);
    *(uint32_t*)p = *(const uint32_t*)&h;
}

// ---------------------------------------------------------------------------
// fp32 -> fp16 conversion (RNE)
// ---------------------------------------------------------------------------
__global__ void to_half_k(const float4* __restrict__ in, uint2* __restrict__ out, int n4)
{
    int i = blockIdx.x * blockDim.x + threadIdx.x;
    if (i < n4) {
        float4 v = in[i];
        __half2 h0 = __floats2half2_rn(v.x, v.y);
        __half2 h1 = __floats2half2_rn(v.z, v.w);
        uint2 u;
        u.x = *(const uint32_t*)&h0;
        u.y = *(const uint32_t*)&h1;
        out[i] = u;
    }
}

// ---------------------------------------------------------------------------
// fp16 GEMM: C[M,N] = A[M,K] @ W[N,K]^T + bias[N]
// BM=128, BN=128, BK=64 halves. 256 thr, 8 warps of 32x64 (acc 64 regs),
// __launch_bounds__(256,2) -> 2 CTAs/SM = 16 warps/SM for latency hiding.
// cp.async double-buffered smem (halves, row stride 72).
// half_out: 1 -> C is __half, else float.
// ---------------------------------------------------------------------------
__global__ void __launch_bounds__(256, 2)
gemm_h(const __half* __restrict__ A, int lda,
       const __half* __restrict__ W, int ldw,
       void* __restrict__ Cv, int ldc,
       int K, const float* __restrict__ bias, int half_out)
{
    constexpr int LDH = 72;    // halves per row (64 + 8 pad)
    extern __shared__ __half smh[];
    __half* As = smh;                    // [2][128][72]
    __half* Bs = smh + 2 * 128 * LDH;    // [2][128][72]

    const int tid = threadIdx.x, lane = tid & 31, wid = tid >> 5;
    const int warpM = (wid & 3) * 32, warpN = (wid >> 2) * 64;
    const long long m0 = (long long)blockIdx.y * 128;
    const long long n0 = (long long)blockIdx.x * 128;

    float acc[2][8][4] = {};

    auto issue = [&](int it, int buf) {
        const long long k0 = (long long)it * 64;
        __half* ad = As + buf * 128 * LDH;
        #pragma unroll
        for (int i = 0; i < 4; ++i) {
            int lin = i * 256 + tid;
            int r = lin >> 3, c8 = (lin & 7) * 8;
            cp16(smem_u32(ad + r * LDH + c8), A + (m0 + r) * lda + k0 + c8);
        }
        __half* bd = Bs + buf * 128 * LDH;
        #pragma unroll
        for (int i = 0; i < 4; ++i) {
            int lin = i * 256 + tid;
            int r = lin >> 3, c8 = (lin & 7) * 8;
            cp16(smem_u32(bd + r * LDH + c8), W + (n0 + r) * ldw + k0 + c8);
        }
        cp_commit();
    };

    const int NIT = K / 64;
    issue(0, 0);
    int buf = 0;
    for (int it = 0; it < NIT; ++it) {
        cp_wait<0>();
        __syncthreads();
        if (it + 1 < NIT) issue(it + 1, buf ^ 1);

        const __half* a = As + buf * 128 * LDH;
        const __half* b = Bs + buf * 128 * LDH;
        #pragma unroll
        for (int k16 = 0; k16 < 4; ++k16) {
            const int kb = k16 * 16 + 2 * (lane & 3);
            uint32_t af[2][4];
            #pragma unroll
            for (int im = 0; im < 2; ++im) {
                int r = warpM + im * 16 + (lane >> 2);
                af[im][0] = ldh2(a + r * LDH + kb);
                af[im][1] = ldh2(a + (r + 8) * LDH + kb);
                af[im][2] = ldh2(a + r * LDH + kb + 8);
                af[im][3] = ldh2(a + (r + 8) * LDH + kb + 8);
            }
            #pragma unroll
            for (int in = 0; in < 8; ++in) {
                int nn = warpN + in * 8 + (lane >> 2);
                uint32_t b0 = ldh2(b + nn * LDH + kb);
                uint32_t b1 = ldh2(b + nn * LDH + kb + 8);
                #pragma unroll
                for (int im = 0; im < 2; ++im)
                    mma_h(acc[im][in], af[im], b0, b1);
            }
        }
        buf ^= 1;
    }

    #pragma unroll
    for (int im = 0; im < 2; ++im) {
        long long r = m0 + warpM + im * 16 + (lane >> 2);
        #pragma unroll
        for (int in = 0; in < 8; ++in) {
            long long c = n0 + warpN + in * 8 + 2 * (lane & 3);
            float b0 = bias[c], b1 = bias[c + 1];
            float v0 = acc[im][in][0] + b0, v1 = acc[im][in][1] + b1;
            float v2 = acc[im][in][2] + b0, v3 = acc[im][in][3] + b1;
            if (half_out) {
                __half* Ch = (__half*)Cv;
                sth2(Ch + r * ldc + c, v0, v1);
                sth2(Ch + (r + 8) * ldc + c, v2, v3);
            } else {
                float* Cf = (float*)Cv;
                *(float2*)&Cf[r * ldc + c]       = make_float2(v0, v1);
                *(float2*)&Cf[(r + 8) * ldc + c] = make_float2(v2, v3);
            }
        }
    }
}

// ---------------------------------------------------------------------------
// Fused fp16 attention. TM = Q-rows per warp (16 local, 32 global).
// CTA: QT=8*TM Q-rows, key chunks of 64, online softmax, additive +1 mask.
// V transposed in smem (fp16 B-fragments need k-contiguity).
// smem halves: sQ[QT][72] | sP[QT][72] | sK[2][64][72] | sV[2][64][72] | sVt[64][72]
// ---------------------------------------------------------------------------
template<int TM>
__global__ void __launch_bounds__(256, 1)
attn_h(const __half* __restrict__ qkv, __half* __restrict__ ao, int W, int nc)
{
    constexpr int QT = TM * 8;
    constexpr int MT = TM / 16;
    constexpr int NH = TM / 8;
    constexpr int LDH = 72;
    extern __shared__ __half smh[];
    __half* sQ = smh;                         // QT x 72
    __half* sP = sQ + QT * LDH;               // QT x 72
    __half* sK = sP + QT * LDH;               // 2 x 64 x 72
    __half* sV = sK + 2 * 64 * LDH;           // 2 x 64 x 72
    __half* sVt = sV + 2 * 64 * LDH;          // 64 x 72

    const int tid = threadIdx.x, lane = tid & 31, wid = tid >> 5;
    const int wm = wid * TM;
    const int pair = blockIdx.y;
    const int win = pair >> 4, h = pair & 15;
    const int q0 = blockIdx.x * QT;
    const long long base = (long long)win * W * 3072 + h * 64;
    const __half* Qg = qkv + base + (long long)q0 * 3072;
    const __half* Kg = qkv + base + 1024;
    const __half* Vg = qkv + base + 2048;

    // stage Q: QT rows x 8 cp16
    #pragma unroll
    for (int i = 0; i < QT / 32; ++i) {
        int lin = i * 256 + tid;
        int r = lin >> 3, c8 = (lin & 7) * 8;
        cp16(smem_u32(sQ + r * LDH + c8), Qg + (long long)r * 3072 + c8);
    }
    cp_commit();

    auto stageKV = [&](int c, int b) {
        #pragma unroll
        for (int i = 0; i < 2; ++i) {
            int lin = i * 256 + tid;
            int r = lin >> 3, c8 = (lin & 7) * 8;
            cp16(smem_u32(sK + b * 64 * LDH + r * LDH + c8),
                 Kg + (long long)(c * 64 + r) * 3072 + c8);
        }
        #pragma unroll
        for (int i = 0; i < 2; ++i) {
            int lin = i * 256 + tid;
            int r = lin >> 3, c8 = (lin & 7) * 8;
            cp16(smem_u32(sV + b * 64 * LDH + r * LDH + c8),
                 Vg + (long long)(c * 64 + r) * 3072 + c8);
        }
        cp_commit();
    };
    stageKV(0, 0);

    float oacc[MT][8][4] = {};
    float m_[NH], l_[NH];
    #pragma unroll
    for (int i = 0; i < NH; ++i) { m_[i] = -1e30f; l_[i] = 0.f; }

    for (int c = 0; c < nc; ++c) {
        const int buf = c & 1;
        if (c + 1 < nc) { stageKV(c + 1, buf ^ 1); cp_wait<1>(); }
        else            { cp_wait<0>(); }
        __syncthreads();   // chunk c visible; prior PV complete

        const __half* kbuf = sK + buf * 64 * LDH;
        const __half* vbuf = sV + buf * 64 * LDH;

        // ---- S = Q K^T (warp: TM rows x 64 keys, D=64 = 4 k16 steps) ----
        float sacc[MT][8][4];
        #pragma unroll
        for (int im = 0; im < MT; ++im)
            #pragma unroll
            for (int in = 0; in < 8; ++in)
                sacc[im][in][0] = sacc[im][in][1] = sacc[im][in][2] = sacc[im][in][3] = 0.f;

        #pragma unroll
        for (int k16 = 0; k16 < 4; ++k16) {
            const int kb = k16 * 16 + 2 * (lane & 3);
            uint32_t af[MT][4];
            #pragma unroll
            for (int im = 0; im < MT; ++im) {
                int r = wm + im * 16 + (lane >> 2);
                af[im][0] = ldh2(sQ + r * LDH + kb);
                af[im][1] = ldh2(sQ + (r + 8) * LDH + kb);
                af[im][2] = ldh2(sQ + r * LDH + kb + 8);
                af[im][3] = ldh2(sQ + (r + 8) * LDH + kb + 8);
            }
            #pragma unroll
            for (int in = 0; in < 8; ++in) {
                int nn = in * 8 + (lane >> 2);
                uint32_t b0 = ldh2(kbuf + nn * LDH + kb);
                uint32_t b1 = ldh2(kbuf + nn * LDH + kb + 8);
                #pragma unroll
                for (int im = 0; im < MT; ++im)
                    mma_h(sacc[im][in], af[im], b0, b1);
            }
        }

        // ---- transpose V chunk: sV[key][dim] -> sVt[dim][key] (2x2 blocks) ----
        #pragma unroll
        for (int i = 0; i < 4; ++i) {
            int idx = i * 256 + tid;           // 1024 2x2 blocks
            int bk = idx >> 5, bd = idx & 31;  // key block, dim block
            __half2 va = *(const __half2*)&vbuf[(2 * bk) * LDH + 2 * bd];
            __half2 vb = *(const __half2*)&vbuf[(2 * bk + 1) * LDH + 2 * bd];
            *(__half2*)&sVt[(2 * bd) * LDH + 2 * bk]     = __lows2half2(va, vb);
            *(__half2*)&sVt[(2 * bd + 1) * LDH + 2 * bk] = __highs2half2(va, vb);
        }

        // ---- online softmax (ADDITIVE +1.0 mask for col > row) ----
        float sscale[NH];
        #pragma unroll
        for (int hh = 0; hh < NH; ++hh) {
            const int im = hh >> 1, half = hh & 1;
            const int rw = q0 + wm + im * 16 + (lane >> 2) + 8 * half;
            float cm = -1e30f;
            #pragma unroll
            for (int in = 0; in < 8; ++in) {
                int col = c * 64 + in * 8 + 2 * (lane & 3);
                float v0 = sacc[im][in][2 * half]     * 0.125f + ((col     > rw) ? 1.f : 0.f);
                float v1 = sacc[im][in][2 * half + 1] * 0.125f + ((col + 1 > rw) ? 1.f : 0.f);
                sacc[im][in][2 * half] = v0; sacc[im][in][2 * half + 1] = v1;
                cm = fmaxf(cm, fmaxf(v0, v1));
            }
            cm = fmaxf(cm, __shfl_xor_sync(0xffffffffu, cm, 1));
            cm = fmaxf(cm, __shfl_xor_sync(0xffffffffu, cm, 2));
            float mn = fmaxf(m_[hh], cm);
            float sc = __expf(m_[hh] - mn);
            float rs = 0.f;
            const int rloc = wm + im * 16 + (lane >> 2) + 8 * half;
            #pragma unroll
            for (int in = 0; in < 8; ++in) {
                float p0 = __expf(sacc[im][in][2 * half] - mn);
                float p1 = __expf(sacc[im][in][2 * half + 1] - mn);
                rs += p0 + p1;
                sth2(sP + rloc * LDH + in * 8 + 2 * (lane & 3), p0, p1);
            }
            rs += __shfl_xor_sync(0xffffffffu, rs, 1);
            rs += __shfl_xor_sync(0xffffffffu, rs, 2);
            l_[hh] = l_[hh] * sc + rs;
            m_[hh] = mn;
            sscale[hh] = sc;
        }
        #pragma unroll
        for (int im = 0; im < MT; ++im)
            #pragma unroll
            for (int in = 0; in < 8; ++in) {
                oacc[im][in][0] *= sscale[2 * im];
                oacc[im][in][1] *= sscale[2 * im];
                oacc[im][in][2] *= sscale[2 * im + 1];
                oacc[im][in][3] *= sscale[2 * im + 1];
            }

        __syncthreads();   // sVt visible to all warps (sP rows warp-private)

        // ---- O += P V  (k = 64 keys = 4 k16 steps; B from sVt[dim][key]) ----
        #pragma unroll
        for (int k16 = 0; k16 < 4; ++k16) {
            const int kb = k16 * 16 + 2 * (lane & 3);
            uint32_t af[MT][4];
            #pragma unroll
            for (int im = 0; im < MT; ++im) {
                int r = wm + im * 16 + (lane >> 2);
                af[im][0] = ldh2(sP + r * LDH + kb);
                af[im][1] = ldh2(sP + (r + 8) * LDH + kb);
                af[im][2] = ldh2(sP + r * LDH + kb + 8);
                af[im][3] = ldh2(sP + (r + 8) * LDH + kb + 8);
            }
            #pragma unroll
            for (int in = 0; in < 8; ++in) {
                int nn = in * 8 + (lane >> 2);
                uint32_t b0 = ldh2(sVt + nn * LDH + kb);
                uint32_t b1 = ldh2(sVt + nn * LDH + kb + 8);
                #pragma unroll
                for (int im = 0; im < MT; ++im)
                    mma_h(oacc[im][in], af[im], b0, b1);
            }
        }
        __syncthreads();   // all reads done before next stage overwrites buffers
    }

    // ---- epilogue: O /= l -> fp16 ao ----
    #pragma unroll
    for (int im = 0; im < MT; ++im)
        #pragma unroll
        for (int half = 0; half < 2; ++half) {
            const int hh = 2 * im + half;
            const float inv = 1.f / l_[hh];
            const long long trow = (long long)win * W + q0 + wm + im * 16
                                   + (lane >> 2) + 8 * half;
            __half* Od = ao + trow * 1024 + h * 64;
            #pragma unroll
            for (int in = 0; in < 8; ++in) {
                int cc = in * 8 + 2 * (lane & 3);
                sth2(Od + cc, oacc[im][in][2 * half] * inv,
                              oacc[im][in][2 * half + 1] * inv);
            }
        }
}

// ---------------------------------------------------------------------------
// driver
// ---------------------------------------------------------------------------
static const int GEMM_SMEM = 2 * (128 * 72 + 128 * 72) * 2;               // 73728
static const int ATTN16_SMEM = (2 * 128 * 72 + 5 * 64 * 72) * 2;          // 82944
static const int ATTN32_SMEM = (2 * 256 * 72 + 5 * 64 * 72) * 2;          // 119808

static void run_branch(const float* x, const float* w_in, const float* b_in,
                       const float* w_out, const float* b_out,
                       int W, float* out,
                       __half* qkv, __half* ao, __half* rX, __half* rW, __half* rWo)
{
    to_half_k<<<16384, 256>>>((const float4*)x, (uint2*)rX, 16384 * 1024 / 4);
    to_half_k<<<3072, 256>>>((const float4*)w_in, (uint2*)rW, 3072 * 1024 / 4);
    to_half_k<<<1024, 256>>>((const float4*)w_out, (uint2*)rWo, 1024 * 1024 / 4);

    // QKV projection -> fp16 qkv
    gemm_h<<<dim3(3072 / 128, 16384 / 128), 256, GEMM_SMEM>>>(
        rX, Dd, rW, Dd, qkv, 3072, Dd, b_in, 1);

    if (W == 128)
        attn_h<16><<<dim3(1, (16384 / 128) * Hh), 256, ATTN16_SMEM>>>(qkv, ao, W, 2);
    else
        attn_h<32><<<dim3(W / 256, (16384 / W) * Hh), 256, ATTN32_SMEM>>>(qkv, ao, W, 16);

    // out projection -> fp32 out
    gemm_h<<<dim3(1024 / 128, 16384 / 128), 256, GEMM_SMEM>>>(
        ao, Dd, rWo, Dd, out, Dd, Dd, b_out, 0);
}

extern "C" void kernel_launch(void* const* d_in, const int* in_sizes, int n_in,
                              void* d_out, int out_size)
{
    const float* lqs    = (const float*)d_in[0];
    const float* gqs    = (const float*)d_in[1];
    const float* wl_in  = (const float*)d_in[2];
    const float* bl_in  = (const float*)d_in[3];
    const float* wl_out = (const float*)d_in[4];
    const float* bl_out = (const float*)d_in[5];
    const float* wg_in  = (const float*)d_in[6];
    const float* bg_in  = (const float*)d_in[7];
    const float* wg_out = (const float*)d_in[8];
    const float* bg_out = (const float*)d_in[9];
    float* out = (float*)d_out;

    cudaFuncSetAttribute(gemm_h, cudaFuncAttributeMaxDynamicSharedMemorySize, GEMM_SMEM);
    cudaFuncSetAttribute(attn_h<16>, cudaFuncAttributeMaxDynamicSharedMemorySize, ATTN16_SMEM);
    cudaFuncSetAttribute(attn_h<32>, cudaFuncAttributeMaxDynamicSharedMemorySize, ATTN32_SMEM);

    __half *qkv, *ao, *rX, *rW, *rWo;
    cudaGetSymbolAddress((void**)&qkv, g_qkvh);
    cudaGetSymbolAddress((void**)&ao, g_aoh);
    cudaGetSymbolAddress((void**)&rX, g_rxh);
    cudaGetSymbolAddress((void**)&rW, g_rwh);
    cudaGetSymbolAddress((void**)&rWo, g_rwoh);

    run_branch(lqs, wl_in, bl_in, wl_out, bl_out, 128, out, qkv, ao, rX, rW, rWo);
    run_branch(gqs, wg_in, bg_in, wg_out, bg_out, 1024,
               out + (size_t)Bb * Ss * Dd, qkv, ao, rX, rW, rWo);
}